// round 1
// baseline (speedup 1.0000x reference)
#include <cuda_runtime.h>
#include <math.h>

// ---------------------------------------------------------------------------
// DWFormerBlock: windowed local transformer + window-level global transformer.
// Round 1: correct fp32 implementation, SIMT tiled GEMMs, no atomics,
// graph-capturable (kernel launches only), allocation-free (__device__ scratch).
// ---------------------------------------------------------------------------

constexpr int cB  = 16;
constexpr int cT  = 768;
constexpr int cF  = 512;
constexpr int cFF = 2048;
constexpr int cH  = 8;
constexpr int cDH = 64;
constexpr int BT  = cB * cT;       // 12288
constexpr int TT  = cT * cT;       // 589824
constexpr float NEGVAL = -1e30f;

// ------------------------------- scratch -----------------------------------
__device__ float g_xl [BT * cF];
__device__ float g_q  [BT * cF];
__device__ float g_k  [BT * cF];
__device__ float g_v  [BT * cF];
__device__ float g_S  [cB * cH * TT];     // 302 MB attention scores/probs
__device__ float g_ao [BT * cF];
__device__ float g_pj [BT * cF];
__device__ float g_y  [BT * cF];
__device__ float g_h  [BT * cFF];
__device__ float g_lx [BT * cF];
__device__ float g_gy [BT * cF];
__device__ float g_pre[BT * cF];
__device__ float g_ls [BT];
__device__ float g_h2 [BT];
__device__ float g_wise[BT];
__device__ float g_part[16 * BT];
__device__ int   g_wid[BT];
__device__ int   g_nb [cB];
__device__ int   g_ws [cB * (cT + 1)];

// --------------------------- reduction helpers -----------------------------
__device__ __forceinline__ float redMax256(float v) {
    __shared__ float sm[8];
#pragma unroll
    for (int o = 16; o > 0; o >>= 1) v = fmaxf(v, __shfl_xor_sync(0xffffffffu, v, o));
    if ((threadIdx.x & 31) == 0) sm[threadIdx.x >> 5] = v;
    __syncthreads();
    if (threadIdx.x == 0) {
        float m = sm[0];
#pragma unroll
        for (int i = 1; i < 8; i++) m = fmaxf(m, sm[i]);
        sm[0] = m;
    }
    __syncthreads();
    float r = sm[0];
    __syncthreads();
    return r;
}

__device__ __forceinline__ float redSum256(float v) {
    __shared__ float sm[8];
#pragma unroll
    for (int o = 16; o > 0; o >>= 1) v += __shfl_xor_sync(0xffffffffu, v, o);
    if ((threadIdx.x & 31) == 0) sm[threadIdx.x >> 5] = v;
    __syncthreads();
    if (threadIdx.x == 0) {
        float s = 0.f;
#pragma unroll
        for (int i = 0; i < 8; i++) s += sm[i];
        sm[0] = s;
    }
    __syncthreads();
    float r = sm[0];
    __syncthreads();
    return r;
}

// ------------------------------- masks kernel ------------------------------
// One block per batch: bitonic-sort halting scores, pick threshold, build
// window ids / window starts / wise, write thresholds straight into d_out.
__global__ void masks_kernel(const float* __restrict__ hs, const float* __restrict__ msk,
                             float* __restrict__ thr_out, int* __restrict__ wid,
                             int* __restrict__ nbarr, int* __restrict__ ws,
                             float* __restrict__ wise) {
    int b = blockIdx.x, tid = threadIdx.x;
    __shared__ float ss[1024];
    __shared__ int a1[cT];
    __shared__ int x3[cT];
    __shared__ float red[256];
    __shared__ float sthr;

    for (int i = tid; i < 1024; i += 256)
        ss[i] = (i < cT) ? hs[b * cT + i] : 3.402823466e38f;
    __syncthreads();

    // bitonic sort ascending, n = 1024
    for (int k2 = 2; k2 <= 1024; k2 <<= 1) {
        for (int j = k2 >> 1; j > 0; j >>= 1) {
            for (int i = tid; i < 1024; i += 256) {
                int l = i ^ j;
                if (l > i) {
                    float a = ss[i], c = ss[l];
                    bool up = ((i & k2) == 0);
                    if ((a > c) == up) { ss[i] = c; ss[l] = a; }
                }
            }
            __syncthreads();
        }
    }

    // mask1 = sum(1 - mask)
    float m1 = 0.f;
    for (int i = tid; i < cT; i += 256) m1 += 1.0f - msk[b * cT + i];
    red[tid] = m1; __syncthreads();
    for (int s = 128; s > 0; s >>= 1) {
        if (tid < s) red[tid] += red[tid + s];
        __syncthreads();
    }
    if (tid == 0) {
        float mm = red[0];
        int med = (int)(mm * 0.5f + (float)cT - mm);
        if (med > cT - 1) med = cT - 1;
        if (med < 0) med = 0;
        sthr = ss[med];
        thr_out[b] = sthr;
    }
    __syncthreads();
    float thr = sthr;

    for (int i = tid; i < cT; i += 256) {
        int keep = (hs[b * cT + i] >= thr) ? 1 : 0;
        a1[i] = keep;
        wise[b * cT + i] = keep ? 1.0f : 0.85f;
    }
    __syncthreads();
    for (int i = tid; i < cT; i += 256) {
        int x2 = (i < cT - 1) ? a1[i + 1] : (1 - a1[cT - 1]);
        x3[i] = (x2 != a1[i]) ? 1 : 0;
    }
    __syncthreads();
    if (tid == 0) {
        int c = 0;
        ws[b * (cT + 1)] = 0;
        int prev = 0;
        for (int t = 0; t < cT; t++) {
            int xt = x3[t];
            int xm = (xt == 1 && prev == 1) ? 0 : xt;   // suppress double boundary
            if (t == cT - 1) xm = 1;                    // force last boundary
            prev = xt;
            wid[b * cT + t] = c;
            if (xm) { c++; ws[b * (cT + 1) + c] = t + 1; }
        }
        nbarr[b] = c;
    }
}

// ------------------------------ layernorm ----------------------------------
// Y = LN(X [+ R]); F = 512 fixed; 128 threads x float4.
__global__ void ln_kernel(const float* __restrict__ X, const float* __restrict__ R,
                          float* __restrict__ Y) {
    long row = blockIdx.x;
    float4 v = ((const float4*)(X + row * cF))[threadIdx.x];
    if (R) {
        float4 r = ((const float4*)(R + row * cF))[threadIdx.x];
        v.x += r.x; v.y += r.y; v.z += r.z; v.w += r.w;
    }
    float s = v.x + v.y + v.z + v.w;
    float q = v.x * v.x + v.y * v.y + v.z * v.z + v.w * v.w;
    __shared__ float rs[4], rq[4];
#pragma unroll
    for (int o = 16; o > 0; o >>= 1) {
        s += __shfl_down_sync(0xffffffffu, s, o);
        q += __shfl_down_sync(0xffffffffu, q, o);
    }
    int w = threadIdx.x >> 5;
    if ((threadIdx.x & 31) == 0) { rs[w] = s; rq[w] = q; }
    __syncthreads();
    s = rs[0] + rs[1] + rs[2] + rs[3];
    q = rq[0] + rq[1] + rq[2] + rq[3];
    float mean = s * (1.0f / cF);
    float var  = q * (1.0f / cF) - mean * mean;
    float inv  = rsqrtf(var + 1e-5f);
    float4 o4 = make_float4((v.x - mean) * inv, (v.y - mean) * inv,
                            (v.z - mean) * inv, (v.w - mean) * inv);
    ((float4*)(Y + row * cF))[threadIdx.x] = o4;
}

// --------------------------------- GEMM ------------------------------------
// C = alpha * A * op(B); 64x64 tile, BK=16, 256 threads, 4x4 per thread.
// Two-level batch (b = z/Hdiv, h = z%Hdiv) with separate strides.
template <bool TRANSB, bool RELU>
__global__ void __launch_bounds__(256)
gemm_k(const float* __restrict__ A, const float* __restrict__ Bm, float* __restrict__ C,
       int K, int lda, int ldb, int ldc,
       long sAb, long sAh, long sBb, long sBh, long sCb, long sCh,
       int Hdiv, float alpha) {
    int z  = blockIdx.z;
    int bb = z / Hdiv, hh = z - bb * Hdiv;
    A  += (long)bb * sAb + (long)hh * sAh;
    Bm += (long)bb * sBb + (long)hh * sBh;
    C  += (long)bb * sCb + (long)hh * sCh;

    __shared__ float As[16][68];
    __shared__ float Bs[16][68];
    int tid = threadIdx.x;
    int tx = tid & 15, ty = tid >> 4;
    int m0 = blockIdx.y * 64, n0 = blockIdx.x * 64;
    float acc[4][4] = {};

    for (int k0 = 0; k0 < K; k0 += 16) {
        {   // A tile (transposed into smem): rows m0..m0+63, cols k0..k0+15
            int m  = tid >> 2;
            int kq = (tid & 3) << 2;
            float4 a4 = *(const float4*)(A + (long)(m0 + m) * lda + k0 + kq);
            As[kq + 0][m] = a4.x; As[kq + 1][m] = a4.y;
            As[kq + 2][m] = a4.z; As[kq + 3][m] = a4.w;
        }
        if (TRANSB) {   // B is N x K row-major
            int n  = tid >> 2;
            int kq = (tid & 3) << 2;
            float4 b4 = *(const float4*)(Bm + (long)(n0 + n) * ldb + k0 + kq);
            Bs[kq + 0][n] = b4.x; Bs[kq + 1][n] = b4.y;
            Bs[kq + 2][n] = b4.z; Bs[kq + 3][n] = b4.w;
        } else {        // B is K x N row-major
            int kk = tid >> 4;
            int nq = (tid & 15) << 2;
            *(float4*)&Bs[kk][nq] = *(const float4*)(Bm + (long)(k0 + kk) * ldb + n0 + nq);
        }
        __syncthreads();
#pragma unroll
        for (int k = 0; k < 16; k++) {
            float4 a4 = *(const float4*)&As[k][ty << 2];
            float4 b4 = *(const float4*)&Bs[k][tx << 2];
            float av[4] = {a4.x, a4.y, a4.z, a4.w};
            float bv[4] = {b4.x, b4.y, b4.z, b4.w};
#pragma unroll
            for (int i = 0; i < 4; i++)
#pragma unroll
                for (int j = 0; j < 4; j++)
                    acc[i][j] = fmaf(av[i], bv[j], acc[i][j]);
        }
        __syncthreads();
    }
#pragma unroll
    for (int i = 0; i < 4; i++) {
        float4 o;
        o.x = acc[i][0] * alpha; o.y = acc[i][1] * alpha;
        o.z = acc[i][2] * alpha; o.w = acc[i][3] * alpha;
        if (RELU) {
            o.x = fmaxf(o.x, 0.f); o.y = fmaxf(o.y, 0.f);
            o.z = fmaxf(o.z, 0.f); o.w = fmaxf(o.w, 0.f);
        }
        *(float4*)(C + (long)(m0 + (ty << 2) + i) * ldc + n0 + (tx << 2)) = o;
    }
}

// ------------------------------ softmax ------------------------------------
// One block per attention row. mode 0: local (same-window keys only, via wid).
// mode 1: global (keys k < nb[b]).
__global__ void softmax_k(float* __restrict__ S, const int* __restrict__ wid,
                          const int* __restrict__ nbarr, int mode) {
    long r = blockIdx.x;
    int b  = (int)(r / ((long)cH * cT));
    int qi = (int)(r % cT);
    float* row = S + r * (long)cT;
    int tid = threadIdx.x;
    float xv[3];
    if (mode == 0) {
        int wq = __ldg(&wid[b * cT + qi]);
#pragma unroll
        for (int i = 0; i < 3; i++) {
            int k = tid + i * 256;
            float v = row[k];
            xv[i] = (__ldg(&wid[b * cT + k]) == wq) ? v : NEGVAL;
        }
    } else {
        int lim = __ldg(&nbarr[b]);
#pragma unroll
        for (int i = 0; i < 3; i++) {
            int k = tid + i * 256;
            float v = row[k];
            xv[i] = (k < lim) ? v : NEGVAL;
        }
    }
    float mx = redMax256(fmaxf(fmaxf(xv[0], xv[1]), xv[2]));
    float e[3];
    float s = 0.f;
#pragma unroll
    for (int i = 0; i < 3; i++) { e[i] = expf(xv[i] - mx); s += e[i]; }
    s = redSum256(s);
    float inv = 1.0f / s;
#pragma unroll
    for (int i = 0; i < 3; i++) row[tid + i * 256] = e[i] * inv;
}

// ------------------ column mean of probs (score / hh2) ---------------------
__global__ void colsum_part(const float* __restrict__ S, float* __restrict__ part) {
    int b = blockIdx.y;
    int k = blockIdx.x * 128 + threadIdx.x;
    int z = blockIdx.z;                       // 16 splits of H*T rows
    const int RPS = cH * cT / 16;             // 384
    const float* base = S + (long)b * cH * TT + (long)z * RPS * cT + k;
    float s = 0.f;
#pragma unroll 8
    for (int r = 0; r < RPS; r++) s += base[(long)r * cT];
    part[(long)z * BT + b * cT + k] = s;
}

__global__ void colsum_fin(const float* __restrict__ part, float* __restrict__ outv,
                           float scale) {
    int i = blockIdx.x * 256 + threadIdx.x;
    if (i < BT) {
        float s = 0.f;
#pragma unroll
        for (int z = 0; z < 16; z++) s += part[(long)z * BT + i];
        outv[i] = s * scale;
    }
}

// ------------------- window aggregation: pre[b,w,:] ------------------------
__global__ void pre_kernel(const float* __restrict__ lx, const float* __restrict__ ls,
                           const int* __restrict__ nbarr, const int* __restrict__ ws,
                           float* __restrict__ pre) {
    int b = blockIdx.y, w = blockIdx.x, tid = threadIdx.x;   // 128 threads x float4
    float4 acc = make_float4(0.f, 0.f, 0.f, 0.f);
    if (w < nbarr[b]) {
        int s = ws[b * (cT + 1) + w];
        int e = ws[b * (cT + 1) + w + 1];
        for (int t = s; t < e; t++) {
            float sc = __ldg(&ls[b * cT + t]);
            float4 v = ((const float4*)(lx + ((long)b * cT + t) * cF))[tid];
            acc.x = fmaf(v.x, sc, acc.x); acc.y = fmaf(v.y, sc, acc.y);
            acc.z = fmaf(v.z, sc, acc.z); acc.w = fmaf(v.w, sc, acc.w);
        }
    }
    ((float4*)(pre + ((long)b * cT + w) * cF))[tid] = acc;
}

// --------------------------- misc elementwise ------------------------------
__global__ void scale_kernel(float* __restrict__ yx, const float* __restrict__ wise) {
    long row = blockIdx.x;
    float sc = wise[row];
    float4 v = ((const float4*)(yx + row * cF))[threadIdx.x];
    v.x *= sc; v.y *= sc; v.z *= sc; v.w *= sc;
    ((float4*)(yx + row * cF))[threadIdx.x] = v;
}

__global__ void final_data(const float* __restrict__ lx, const float* __restrict__ gy,
                           const int* __restrict__ wid, float* __restrict__ outd) {
    long i = blockIdx.x;           // token row b*T + t
    int b = (int)(i / cT);
    int w = wid[i];
    float4 a = ((const float4*)(lx + i * cF))[threadIdx.x];
    float4 g = ((const float4*)(gy + ((long)b * cT + w) * cF))[threadIdx.x];
    a.x += g.x; a.y += g.y; a.z += g.z; a.w += g.w;
    ((float4*)(outd + i * cF))[threadIdx.x] = a;
}

__global__ void final_attn(const float* __restrict__ ls, const float* __restrict__ h2,
                           const int* __restrict__ wid, float* __restrict__ outa) {
    int b = blockIdx.x, tid = threadIdx.x;
    float xv[3];
#pragma unroll
    for (int i = 0; i < 3; i++) {
        int t = tid + i * 256;
        xv[i] = ls[b * cT + t] * h2[b * cT + wid[b * cT + t]];
    }
    float mx = redMax256(fmaxf(fmaxf(xv[0], xv[1]), xv[2]));
    float e[3];
    float s = 0.f;
#pragma unroll
    for (int i = 0; i < 3; i++) { e[i] = expf(xv[i] - mx); s += e[i]; }
    s = redSum256(s);
    float inv = 1.0f / s;
#pragma unroll
    for (int i = 0; i < 3; i++) outa[b * cT + tid + i * 256] = e[i] * inv;
}

// ------------------------------ host side ----------------------------------
static void run_transformer(const float* xin,
                            const float* Wq, const float* Wk, const float* Wv,
                            const float* Wo, const float* W1, const float* W2,
                            float* yout, float* score, int mode,
                            float* q, float* k, float* v, float* S, float* ao,
                            float* pj, float* y, float* h, float* part,
                            const int* wid, const int* nb) {
    // QKV projections
    gemm_k<false, false><<<dim3(cF / 64, BT / 64, 1), 256>>>(
        xin, Wq, q, cF, cF, cF, cF, 0, 0, 0, 0, 0, 0, 1, 1.f);
    gemm_k<false, false><<<dim3(cF / 64, BT / 64, 1), 256>>>(
        xin, Wk, k, cF, cF, cF, cF, 0, 0, 0, 0, 0, 0, 1, 1.f);
    gemm_k<false, false><<<dim3(cF / 64, BT / 64, 1), 256>>>(
        xin, Wv, v, cF, cF, cF, cF, 0, 0, 0, 0, 0, 0, 1, 1.f);
    // scores = Q K^T / sqrt(dh)   (batched over B*H)
    gemm_k<true, false><<<dim3(cT / 64, cT / 64, cB * cH), 256>>>(
        q, k, S, cDH, cF, cF, cT,
        (long)cT * cF, (long)cDH, (long)cT * cF, (long)cDH,
        (long)cH * TT, (long)TT, cH, 0.125f);
    softmax_k<<<cB * cH * cT, 256>>>(S, wid, nb, mode);
    colsum_part<<<dim3(cT / 128, cB, 16), 128>>>(S, part);
    colsum_fin<<<(BT + 255) / 256, 256>>>(part, score, 1.0f / (cH * cT));
    // out = A V  (batched over B*H)
    gemm_k<false, false><<<dim3(1, cT / 64, cB * cH), 256>>>(
        S, v, ao, cT, cT, cF, cF,
        (long)cH * TT, (long)TT, (long)cT * cF, (long)cDH,
        (long)cT * cF, (long)cDH, cH, 1.f);
    // Wo projection, residual LN
    gemm_k<false, false><<<dim3(cF / 64, BT / 64, 1), 256>>>(
        ao, Wo, pj, cF, cF, cF, cF, 0, 0, 0, 0, 0, 0, 1, 1.f);
    ln_kernel<<<BT, 128>>>(xin, pj, y);
    // FFN
    gemm_k<false, true><<<dim3(cFF / 64, BT / 64, 1), 256>>>(
        y, W1, h, cF, cF, cFF, cFF, 0, 0, 0, 0, 0, 0, 1, 1.f);
    gemm_k<false, false><<<dim3(cF / 64, BT / 64, 1), 256>>>(
        h, W2, pj, cFF, cFF, cF, cF, 0, 0, 0, 0, 0, 0, 1, 1.f);
    ln_kernel<<<BT, 128>>>(y, pj, yout);
}

extern "C" void kernel_launch(void* const* d_in, const int* in_sizes, int n_in,
                              void* d_out, int out_size) {
    (void)in_sizes; (void)n_in; (void)out_size;
    const float* x   = (const float*)d_in[0];
    const float* hs  = (const float*)d_in[1];
    const float* msk = (const float*)d_in[2];
    const float* lWq = (const float*)d_in[3];
    const float* lWk = (const float*)d_in[4];
    const float* lWv = (const float*)d_in[5];
    const float* lWo = (const float*)d_in[6];
    const float* lW1 = (const float*)d_in[7];
    const float* lW2 = (const float*)d_in[8];
    const float* gWq = (const float*)d_in[9];
    const float* gWk = (const float*)d_in[10];
    const float* gWv = (const float*)d_in[11];
    const float* gWo = (const float*)d_in[12];
    const float* gW1 = (const float*)d_in[13];
    const float* gW2 = (const float*)d_in[14];

    float* out      = (float*)d_out;
    float* out_thr  = out + (long)BT * cF;   // thresholds (B,)
    float* out_attn = out_thr + cB;          // attn (B, T)

    float *xl, *q, *k, *v, *S, *ao, *pj, *y, *h, *lx, *gy, *pre, *ls, *h2, *wise, *part;
    int *wid, *nb, *ws;
    cudaGetSymbolAddress((void**)&xl,   g_xl);
    cudaGetSymbolAddress((void**)&q,    g_q);
    cudaGetSymbolAddress((void**)&k,    g_k);
    cudaGetSymbolAddress((void**)&v,    g_v);
    cudaGetSymbolAddress((void**)&S,    g_S);
    cudaGetSymbolAddress((void**)&ao,   g_ao);
    cudaGetSymbolAddress((void**)&pj,   g_pj);
    cudaGetSymbolAddress((void**)&y,    g_y);
    cudaGetSymbolAddress((void**)&h,    g_h);
    cudaGetSymbolAddress((void**)&lx,   g_lx);
    cudaGetSymbolAddress((void**)&gy,   g_gy);
    cudaGetSymbolAddress((void**)&pre,  g_pre);
    cudaGetSymbolAddress((void**)&ls,   g_ls);
    cudaGetSymbolAddress((void**)&h2,   g_h2);
    cudaGetSymbolAddress((void**)&wise, g_wise);
    cudaGetSymbolAddress((void**)&part, g_part);
    cudaGetSymbolAddress((void**)&wid,  g_wid);
    cudaGetSymbolAddress((void**)&nb,   g_nb);
    cudaGetSymbolAddress((void**)&ws,   g_ws);

    // 1. masks / windows / thresholds
    masks_kernel<<<cB, 256>>>(hs, msk, out_thr, wid, nb, ws, wise);
    // 2. xl = LN(x)
    ln_kernel<<<BT, 128>>>(x, nullptr, xl);
    // 3. local transformer (window-masked attention)
    run_transformer(xl, lWq, lWk, lWv, lWo, lW1, lW2,
                    lx, ls, /*mode=*/0, q, k, v, S, ao, pj, y, h, part, wid, nb);
    // 4. local_x *= wise
    scale_kernel<<<BT, 128>>>(lx, wise);
    // 5. pre[b,w,:] = sum_{t in window w} local_x[b,t,:] * local_score[b,t]
    pre_kernel<<<dim3(cT, cB), 128>>>(lx, ls, nb, ws, pre);
    // 6. preln = LN(pre)
    ln_kernel<<<BT, 128>>>(pre, nullptr, xl);
    // 7. global transformer (valid-window key mask)
    run_transformer(xl, gWq, gWk, gWv, gWo, gW1, gW2,
                    gy, h2, /*mode=*/1, q, k, v, S, ao, pj, y, h, part, wid, nb);
    // 8. data = local_x + gather(global_y)
    final_data<<<BT, 128>>>(lx, gy, wid, out);
    // 9. attn = softmax(local_score * gather(hh2))
    final_attn<<<cB, 256>>>(ls, h2, wid, out_attn);
}

// round 2
// speedup vs baseline: 1.1985x; 1.1985x over previous
#include <cuda_runtime.h>
#include <math.h>

// ---------------------------------------------------------------------------
// DWFormerBlock round 2: 128x128 / 128x64 SIMT fp32 GEMM, 8x8 per thread,
// register-staged double buffering. Everything else unchanged from R1.
// ---------------------------------------------------------------------------

constexpr int cB  = 16;
constexpr int cT  = 768;
constexpr int cF  = 512;
constexpr int cFF = 2048;
constexpr int cH  = 8;
constexpr int cDH = 64;
constexpr int BT  = cB * cT;       // 12288
constexpr int TT  = cT * cT;       // 589824
constexpr float NEGVAL = -1e30f;

// ------------------------------- scratch -----------------------------------
__device__ float g_xl [BT * cF];
__device__ float g_q  [BT * cF];
__device__ float g_k  [BT * cF];
__device__ float g_v  [BT * cF];
__device__ float g_S  [cB * cH * TT];     // 302 MB attention scores/probs
__device__ float g_ao [BT * cF];
__device__ float g_pj [BT * cF];
__device__ float g_y  [BT * cF];
__device__ float g_h  [BT * cFF];
__device__ float g_lx [BT * cF];
__device__ float g_gy [BT * cF];
__device__ float g_pre[BT * cF];
__device__ float g_ls [BT];
__device__ float g_h2 [BT];
__device__ float g_wise[BT];
__device__ float g_part[16 * BT];
__device__ int   g_wid[BT];
__device__ int   g_nb [cB];
__device__ int   g_ws [cB * (cT + 1)];

// --------------------------- reduction helpers -----------------------------
__device__ __forceinline__ float redMax256(float v) {
    __shared__ float sm[8];
#pragma unroll
    for (int o = 16; o > 0; o >>= 1) v = fmaxf(v, __shfl_xor_sync(0xffffffffu, v, o));
    if ((threadIdx.x & 31) == 0) sm[threadIdx.x >> 5] = v;
    __syncthreads();
    if (threadIdx.x == 0) {
        float m = sm[0];
#pragma unroll
        for (int i = 1; i < 8; i++) m = fmaxf(m, sm[i]);
        sm[0] = m;
    }
    __syncthreads();
    float r = sm[0];
    __syncthreads();
    return r;
}

__device__ __forceinline__ float redSum256(float v) {
    __shared__ float sm[8];
#pragma unroll
    for (int o = 16; o > 0; o >>= 1) v += __shfl_xor_sync(0xffffffffu, v, o);
    if ((threadIdx.x & 31) == 0) sm[threadIdx.x >> 5] = v;
    __syncthreads();
    if (threadIdx.x == 0) {
        float s = 0.f;
#pragma unroll
        for (int i = 0; i < 8; i++) s += sm[i];
        sm[0] = s;
    }
    __syncthreads();
    float r = sm[0];
    __syncthreads();
    return r;
}

// ------------------------------- masks kernel ------------------------------
__global__ void masks_kernel(const float* __restrict__ hs, const float* __restrict__ msk,
                             float* __restrict__ thr_out, int* __restrict__ wid,
                             int* __restrict__ nbarr, int* __restrict__ ws,
                             float* __restrict__ wise) {
    int b = blockIdx.x, tid = threadIdx.x;
    __shared__ float ss[1024];
    __shared__ int a1[cT];
    __shared__ int x3[cT];
    __shared__ float red[256];
    __shared__ float sthr;

    for (int i = tid; i < 1024; i += 256)
        ss[i] = (i < cT) ? hs[b * cT + i] : 3.402823466e38f;
    __syncthreads();

    // bitonic sort ascending, n = 1024
    for (int k2 = 2; k2 <= 1024; k2 <<= 1) {
        for (int j = k2 >> 1; j > 0; j >>= 1) {
            for (int i = tid; i < 1024; i += 256) {
                int l = i ^ j;
                if (l > i) {
                    float a = ss[i], c = ss[l];
                    bool up = ((i & k2) == 0);
                    if ((a > c) == up) { ss[i] = c; ss[l] = a; }
                }
            }
            __syncthreads();
        }
    }

    float m1 = 0.f;
    for (int i = tid; i < cT; i += 256) m1 += 1.0f - msk[b * cT + i];
    red[tid] = m1; __syncthreads();
    for (int s = 128; s > 0; s >>= 1) {
        if (tid < s) red[tid] += red[tid + s];
        __syncthreads();
    }
    if (tid == 0) {
        float mm = red[0];
        int med = (int)(mm * 0.5f + (float)cT - mm);
        if (med > cT - 1) med = cT - 1;
        if (med < 0) med = 0;
        sthr = ss[med];
        thr_out[b] = sthr;
    }
    __syncthreads();
    float thr = sthr;

    for (int i = tid; i < cT; i += 256) {
        int keep = (hs[b * cT + i] >= thr) ? 1 : 0;
        a1[i] = keep;
        wise[b * cT + i] = keep ? 1.0f : 0.85f;
    }
    __syncthreads();
    for (int i = tid; i < cT; i += 256) {
        int x2 = (i < cT - 1) ? a1[i + 1] : (1 - a1[cT - 1]);
        x3[i] = (x2 != a1[i]) ? 1 : 0;
    }
    __syncthreads();
    if (tid == 0) {
        int c = 0;
        ws[b * (cT + 1)] = 0;
        int prev = 0;
        for (int t = 0; t < cT; t++) {
            int xt = x3[t];
            int xm = (xt == 1 && prev == 1) ? 0 : xt;
            if (t == cT - 1) xm = 1;
            prev = xt;
            wid[b * cT + t] = c;
            if (xm) { c++; ws[b * (cT + 1) + c] = t + 1; }
        }
        nbarr[b] = c;
    }
}

// ------------------------------ layernorm ----------------------------------
__global__ void ln_kernel(const float* __restrict__ X, const float* __restrict__ R,
                          float* __restrict__ Y) {
    long row = blockIdx.x;
    float4 v = ((const float4*)(X + row * cF))[threadIdx.x];
    if (R) {
        float4 r = ((const float4*)(R + row * cF))[threadIdx.x];
        v.x += r.x; v.y += r.y; v.z += r.z; v.w += r.w;
    }
    float s = v.x + v.y + v.z + v.w;
    float q = v.x * v.x + v.y * v.y + v.z * v.z + v.w * v.w;
    __shared__ float rs[4], rq[4];
#pragma unroll
    for (int o = 16; o > 0; o >>= 1) {
        s += __shfl_down_sync(0xffffffffu, s, o);
        q += __shfl_down_sync(0xffffffffu, q, o);
    }
    int w = threadIdx.x >> 5;
    if ((threadIdx.x & 31) == 0) { rs[w] = s; rq[w] = q; }
    __syncthreads();
    s = rs[0] + rs[1] + rs[2] + rs[3];
    q = rq[0] + rq[1] + rq[2] + rq[3];
    float mean = s * (1.0f / cF);
    float var  = q * (1.0f / cF) - mean * mean;
    float inv  = rsqrtf(var + 1e-5f);
    float4 o4 = make_float4((v.x - mean) * inv, (v.y - mean) * inv,
                            (v.z - mean) * inv, (v.w - mean) * inv);
    ((float4*)(Y + row * cF))[threadIdx.x] = o4;
}

// --------------------------------- GEMM ------------------------------------
// C = alpha * A * op(B). BM x BN CTA tile, BK=8, 8x8 per thread (2x2 float4
// fragments at offsets {0, BM/2} x {0, BN/2}), register-staged double buffer.
template <int BM, int BN, int BK, int NT, bool TRANSB, bool RELU>
__global__ void __launch_bounds__(NT)
gemm2(const float* __restrict__ A, const float* __restrict__ Bm, float* __restrict__ C,
      int K, int lda, int ldb, int ldc,
      long sAb, long sAh, long sBb, long sBh, long sCb, long sCh,
      int Hdiv, float alpha) {
    int z  = blockIdx.z;
    int bb = z / Hdiv, hh = z - bb * Hdiv;
    A  += (long)bb * sAb + (long)hh * sAh;
    Bm += (long)bb * sBb + (long)hh * sBh;
    C  += (long)bb * sCb + (long)hh * sCh;

    constexpr int PAD = 4;
    __shared__ float As[2][BK][BM + PAD];
    __shared__ float Bs[2][BK][BN + PAD];

    constexpr int AI = (BM * BK / 4) / NT;   // float4 loads per thread (A)
    constexpr int BI = (BK * BN / 4) / NT;   // float4 loads per thread (B)
    static_assert(AI * NT * 4 == BM * BK, "A tile size");
    static_assert(BI * NT * 4 == BK * BN, "B tile size");

    int tid = threadIdx.x;
    constexpr int TCOL = BN / 8;             // thread columns
    int tx = tid % TCOL, ty = tid / TCOL;
    int m0 = blockIdx.y * BM, n0 = blockIdx.x * BN;

    float acc[8][8] = {};
    float4 pa[AI], pb[BI];

    // ---- prologue: load k0 = 0 tile ----
#pragma unroll
    for (int i = 0; i < AI; i++) {
        int e = tid + i * NT;
        int m = e / (BK / 4), kq = (e % (BK / 4)) * 4;
        pa[i] = *(const float4*)(A + (long)(m0 + m) * lda + kq);
    }
#pragma unroll
    for (int i = 0; i < BI; i++) {
        int e = tid + i * NT;
        if (TRANSB) {
            int n = e / (BK / 4), kq = (e % (BK / 4)) * 4;
            pb[i] = *(const float4*)(Bm + (long)(n0 + n) * ldb + kq);
        } else {
            int kk = e / (BN / 4), nq = (e % (BN / 4)) * 4;
            pb[i] = *(const float4*)(Bm + (long)kk * ldb + n0 + nq);
        }
    }
#pragma unroll
    for (int i = 0; i < AI; i++) {
        int e = tid + i * NT;
        int m = e / (BK / 4), kq = (e % (BK / 4)) * 4;
        As[0][kq + 0][m] = pa[i].x; As[0][kq + 1][m] = pa[i].y;
        As[0][kq + 2][m] = pa[i].z; As[0][kq + 3][m] = pa[i].w;
    }
#pragma unroll
    for (int i = 0; i < BI; i++) {
        int e = tid + i * NT;
        if (TRANSB) {
            int n = e / (BK / 4), kq = (e % (BK / 4)) * 4;
            Bs[0][kq + 0][n] = pb[i].x; Bs[0][kq + 1][n] = pb[i].y;
            Bs[0][kq + 2][n] = pb[i].z; Bs[0][kq + 3][n] = pb[i].w;
        } else {
            int kk = e / (BN / 4), nq = (e % (BN / 4)) * 4;
            *(float4*)&Bs[0][kk][nq] = pb[i];
        }
    }
    __syncthreads();

    int buf = 0;
    for (int k0 = 0; k0 < K; k0 += BK) {
        bool more = (k0 + BK) < K;
        if (more) {
            int kn = k0 + BK;
#pragma unroll
            for (int i = 0; i < AI; i++) {
                int e = tid + i * NT;
                int m = e / (BK / 4), kq = (e % (BK / 4)) * 4;
                pa[i] = *(const float4*)(A + (long)(m0 + m) * lda + kn + kq);
            }
#pragma unroll
            for (int i = 0; i < BI; i++) {
                int e = tid + i * NT;
                if (TRANSB) {
                    int n = e / (BK / 4), kq = (e % (BK / 4)) * 4;
                    pb[i] = *(const float4*)(Bm + (long)(n0 + n) * ldb + kn + kq);
                } else {
                    int kk = e / (BN / 4), nq = (e % (BN / 4)) * 4;
                    pb[i] = *(const float4*)(Bm + (long)(kn + kk) * ldb + n0 + nq);
                }
            }
        }

        const float (*Asb)[BM + PAD] = As[buf];
        const float (*Bsb)[BN + PAD] = Bs[buf];
#pragma unroll
        for (int k = 0; k < BK; k++) {
            float4 a0 = *(const float4*)&Asb[k][ty * 4];
            float4 a1 = *(const float4*)&Asb[k][BM / 2 + ty * 4];
            float4 b0 = *(const float4*)&Bsb[k][tx * 4];
            float4 b1 = *(const float4*)&Bsb[k][BN / 2 + tx * 4];
            float av[8] = {a0.x, a0.y, a0.z, a0.w, a1.x, a1.y, a1.z, a1.w};
            float bv[8] = {b0.x, b0.y, b0.z, b0.w, b1.x, b1.y, b1.z, b1.w};
#pragma unroll
            for (int i = 0; i < 8; i++)
#pragma unroll
                for (int j = 0; j < 8; j++)
                    acc[i][j] = fmaf(av[i], bv[j], acc[i][j]);
        }

        if (more) {
            int nb2 = buf ^ 1;
#pragma unroll
            for (int i = 0; i < AI; i++) {
                int e = tid + i * NT;
                int m = e / (BK / 4), kq = (e % (BK / 4)) * 4;
                As[nb2][kq + 0][m] = pa[i].x; As[nb2][kq + 1][m] = pa[i].y;
                As[nb2][kq + 2][m] = pa[i].z; As[nb2][kq + 3][m] = pa[i].w;
            }
#pragma unroll
            for (int i = 0; i < BI; i++) {
                int e = tid + i * NT;
                if (TRANSB) {
                    int n = e / (BK / 4), kq = (e % (BK / 4)) * 4;
                    Bs[nb2][kq + 0][n] = pb[i].x; Bs[nb2][kq + 1][n] = pb[i].y;
                    Bs[nb2][kq + 2][n] = pb[i].z; Bs[nb2][kq + 3][n] = pb[i].w;
                } else {
                    int kk = e / (BN / 4), nq = (e % (BN / 4)) * 4;
                    *(float4*)&Bs[nb2][kk][nq] = pb[i];
                }
            }
            __syncthreads();
            buf = nb2;
        }
    }

    // ---- epilogue ----
#pragma unroll
    for (int i = 0; i < 8; i++) {
        int row = m0 + ((i < 4) ? (ty * 4 + i) : (BM / 2 + ty * 4 + i - 4));
        float4 o0, o1;
        o0.x = acc[i][0] * alpha; o0.y = acc[i][1] * alpha;
        o0.z = acc[i][2] * alpha; o0.w = acc[i][3] * alpha;
        o1.x = acc[i][4] * alpha; o1.y = acc[i][5] * alpha;
        o1.z = acc[i][6] * alpha; o1.w = acc[i][7] * alpha;
        if (RELU) {
            o0.x = fmaxf(o0.x, 0.f); o0.y = fmaxf(o0.y, 0.f);
            o0.z = fmaxf(o0.z, 0.f); o0.w = fmaxf(o0.w, 0.f);
            o1.x = fmaxf(o1.x, 0.f); o1.y = fmaxf(o1.y, 0.f);
            o1.z = fmaxf(o1.z, 0.f); o1.w = fmaxf(o1.w, 0.f);
        }
        *(float4*)(C + (long)row * ldc + n0 + tx * 4) = o0;
        *(float4*)(C + (long)row * ldc + n0 + BN / 2 + tx * 4) = o1;
    }
}

// ------------------------------ softmax ------------------------------------
__global__ void softmax_k(float* __restrict__ S, const int* __restrict__ wid,
                          const int* __restrict__ nbarr, int mode) {
    long r = blockIdx.x;
    int b  = (int)(r / ((long)cH * cT));
    int qi = (int)(r % cT);
    float* row = S + r * (long)cT;
    int tid = threadIdx.x;
    float xv[3];
    if (mode == 0) {
        int wq = __ldg(&wid[b * cT + qi]);
#pragma unroll
        for (int i = 0; i < 3; i++) {
            int k = tid + i * 256;
            float v = row[k];
            xv[i] = (__ldg(&wid[b * cT + k]) == wq) ? v : NEGVAL;
        }
    } else {
        int lim = __ldg(&nbarr[b]);
#pragma unroll
        for (int i = 0; i < 3; i++) {
            int k = tid + i * 256;
            float v = row[k];
            xv[i] = (k < lim) ? v : NEGVAL;
        }
    }
    float mx = redMax256(fmaxf(fmaxf(xv[0], xv[1]), xv[2]));
    float e[3];
    float s = 0.f;
#pragma unroll
    for (int i = 0; i < 3; i++) { e[i] = expf(xv[i] - mx); s += e[i]; }
    s = redSum256(s);
    float inv = 1.0f / s;
#pragma unroll
    for (int i = 0; i < 3; i++) row[tid + i * 256] = e[i] * inv;
}

// ------------------ column mean of probs (score / hh2) ---------------------
__global__ void colsum_part(const float* __restrict__ S, float* __restrict__ part) {
    int b = blockIdx.y;
    int k = blockIdx.x * 128 + threadIdx.x;
    int z = blockIdx.z;
    const int RPS = cH * cT / 16;             // 384
    const float* base = S + (long)b * cH * TT + (long)z * RPS * cT + k;
    float s = 0.f;
#pragma unroll 8
    for (int r = 0; r < RPS; r++) s += base[(long)r * cT];
    part[(long)z * BT + b * cT + k] = s;
}

__global__ void colsum_fin(const float* __restrict__ part, float* __restrict__ outv,
                           float scale) {
    int i = blockIdx.x * 256 + threadIdx.x;
    if (i < BT) {
        float s = 0.f;
#pragma unroll
        for (int z = 0; z < 16; z++) s += part[(long)z * BT + i];
        outv[i] = s * scale;
    }
}

// ------------------- window aggregation: pre[b,w,:] ------------------------
__global__ void pre_kernel(const float* __restrict__ lx, const float* __restrict__ ls,
                           const int* __restrict__ nbarr, const int* __restrict__ ws,
                           float* __restrict__ pre) {
    int b = blockIdx.y, w = blockIdx.x, tid = threadIdx.x;
    float4 acc = make_float4(0.f, 0.f, 0.f, 0.f);
    if (w < nbarr[b]) {
        int s = ws[b * (cT + 1) + w];
        int e = ws[b * (cT + 1) + w + 1];
        for (int t = s; t < e; t++) {
            float sc = __ldg(&ls[b * cT + t]);
            float4 v = ((const float4*)(lx + ((long)b * cT + t) * cF))[tid];
            acc.x = fmaf(v.x, sc, acc.x); acc.y = fmaf(v.y, sc, acc.y);
            acc.z = fmaf(v.z, sc, acc.z); acc.w = fmaf(v.w, sc, acc.w);
        }
    }
    ((float4*)(pre + ((long)b * cT + w) * cF))[tid] = acc;
}

// --------------------------- misc elementwise ------------------------------
__global__ void scale_kernel(float* __restrict__ yx, const float* __restrict__ wise) {
    long row = blockIdx.x;
    float sc = wise[row];
    float4 v = ((const float4*)(yx + row * cF))[threadIdx.x];
    v.x *= sc; v.y *= sc; v.z *= sc; v.w *= sc;
    ((float4*)(yx + row * cF))[threadIdx.x] = v;
}

__global__ void final_data(const float* __restrict__ lx, const float* __restrict__ gy,
                           const int* __restrict__ wid, float* __restrict__ outd) {
    long i = blockIdx.x;
    int b = (int)(i / cT);
    int w = wid[i];
    float4 a = ((const float4*)(lx + i * cF))[threadIdx.x];
    float4 g = ((const float4*)(gy + ((long)b * cT + w) * cF))[threadIdx.x];
    a.x += g.x; a.y += g.y; a.z += g.z; a.w += g.w;
    ((float4*)(outd + i * cF))[threadIdx.x] = a;
}

__global__ void final_attn(const float* __restrict__ ls, const float* __restrict__ h2,
                           const int* __restrict__ wid, float* __restrict__ outa) {
    int b = blockIdx.x, tid = threadIdx.x;
    float xv[3];
#pragma unroll
    for (int i = 0; i < 3; i++) {
        int t = tid + i * 256;
        xv[i] = ls[b * cT + t] * h2[b * cT + wid[b * cT + t]];
    }
    float mx = redMax256(fmaxf(fmaxf(xv[0], xv[1]), xv[2]));
    float e[3];
    float s = 0.f;
#pragma unroll
    for (int i = 0; i < 3; i++) { e[i] = expf(xv[i] - mx); s += e[i]; }
    s = redSum256(s);
    float inv = 1.0f / s;
#pragma unroll
    for (int i = 0; i < 3; i++) outa[b * cT + tid + i * 256] = e[i] * inv;
}

// ------------------------------ host side ----------------------------------
static void run_transformer(const float* xin,
                            const float* Wq, const float* Wk, const float* Wv,
                            const float* Wo, const float* W1, const float* W2,
                            float* yout, float* score, int mode,
                            float* q, float* k, float* v, float* S, float* ao,
                            float* pj, float* y, float* h, float* part,
                            const int* wid, const int* nb) {
    // QKV projections (dense 12288 x 512 x 512)
    gemm2<128, 128, 8, 256, false, false><<<dim3(cF / 128, BT / 128, 1), 256>>>(
        xin, Wq, q, cF, cF, cF, cF, 0, 0, 0, 0, 0, 0, 1, 1.f);
    gemm2<128, 128, 8, 256, false, false><<<dim3(cF / 128, BT / 128, 1), 256>>>(
        xin, Wk, k, cF, cF, cF, cF, 0, 0, 0, 0, 0, 0, 1, 1.f);
    gemm2<128, 128, 8, 256, false, false><<<dim3(cF / 128, BT / 128, 1), 256>>>(
        xin, Wv, v, cF, cF, cF, cF, 0, 0, 0, 0, 0, 0, 1, 1.f);
    // scores = Q K^T / sqrt(dh)   (batched over B*H, K = 64)
    gemm2<128, 128, 8, 256, true, false><<<dim3(cT / 128, cT / 128, cB * cH), 256>>>(
        q, k, S, cDH, cF, cF, cT,
        (long)cT * cF, (long)cDH, (long)cT * cF, (long)cDH,
        (long)cH * TT, (long)TT, cH, 0.125f);
    softmax_k<<<cB * cH * cT, 256>>>(S, wid, nb, mode);
    colsum_part<<<dim3(cT / 128, cB, 16), 128>>>(S, part);
    colsum_fin<<<(BT + 255) / 256, 256>>>(part, score, 1.0f / (cH * cT));
    // out = A V  (batched over B*H, N = 64)
    gemm2<128, 64, 8, 128, false, false><<<dim3(1, cT / 128, cB * cH), 128>>>(
        S, v, ao, cT, cT, cF, cF,
        (long)cH * TT, (long)TT, (long)cT * cF, (long)cDH,
        (long)cT * cF, (long)cDH, cH, 1.f);
    // Wo projection, residual LN
    gemm2<128, 128, 8, 256, false, false><<<dim3(cF / 128, BT / 128, 1), 256>>>(
        ao, Wo, pj, cF, cF, cF, cF, 0, 0, 0, 0, 0, 0, 1, 1.f);
    ln_kernel<<<BT, 128>>>(xin, pj, y);
    // FFN
    gemm2<128, 128, 8, 256, false, true><<<dim3(cFF / 128, BT / 128, 1), 256>>>(
        y, W1, h, cF, cF, cFF, cFF, 0, 0, 0, 0, 0, 0, 1, 1.f);
    gemm2<128, 128, 8, 256, false, false><<<dim3(cF / 128, BT / 128, 1), 256>>>(
        h, W2, pj, cFF, cFF, cF, cF, 0, 0, 0, 0, 0, 0, 1, 1.f);
    ln_kernel<<<BT, 128>>>(y, pj, yout);
}

extern "C" void kernel_launch(void* const* d_in, const int* in_sizes, int n_in,
                              void* d_out, int out_size) {
    (void)in_sizes; (void)n_in; (void)out_size;
    const float* x   = (const float*)d_in[0];
    const float* hs  = (const float*)d_in[1];
    const float* msk = (const float*)d_in[2];
    const float* lWq = (const float*)d_in[3];
    const float* lWk = (const float*)d_in[4];
    const float* lWv = (const float*)d_in[5];
    const float* lWo = (const float*)d_in[6];
    const float* lW1 = (const float*)d_in[7];
    const float* lW2 = (const float*)d_in[8];
    const float* gWq = (const float*)d_in[9];
    const float* gWk = (const float*)d_in[10];
    const float* gWv = (const float*)d_in[11];
    const float* gWo = (const float*)d_in[12];
    const float* gW1 = (const float*)d_in[13];
    const float* gW2 = (const float*)d_in[14];

    float* out      = (float*)d_out;
    float* out_thr  = out + (long)BT * cF;   // thresholds (B,)
    float* out_attn = out_thr + cB;          // attn (B, T)

    float *xl, *q, *k, *v, *S, *ao, *pj, *y, *h, *lx, *gy, *pre, *ls, *h2, *wise, *part;
    int *wid, *nb, *ws;
    cudaGetSymbolAddress((void**)&xl,   g_xl);
    cudaGetSymbolAddress((void**)&q,    g_q);
    cudaGetSymbolAddress((void**)&k,    g_k);
    cudaGetSymbolAddress((void**)&v,    g_v);
    cudaGetSymbolAddress((void**)&S,    g_S);
    cudaGetSymbolAddress((void**)&ao,   g_ao);
    cudaGetSymbolAddress((void**)&pj,   g_pj);
    cudaGetSymbolAddress((void**)&y,    g_y);
    cudaGetSymbolAddress((void**)&h,    g_h);
    cudaGetSymbolAddress((void**)&lx,   g_lx);
    cudaGetSymbolAddress((void**)&gy,   g_gy);
    cudaGetSymbolAddress((void**)&pre,  g_pre);
    cudaGetSymbolAddress((void**)&ls,   g_ls);
    cudaGetSymbolAddress((void**)&h2,   g_h2);
    cudaGetSymbolAddress((void**)&wise, g_wise);
    cudaGetSymbolAddress((void**)&part, g_part);
    cudaGetSymbolAddress((void**)&wid,  g_wid);
    cudaGetSymbolAddress((void**)&nb,   g_nb);
    cudaGetSymbolAddress((void**)&ws,   g_ws);

    // 1. masks / windows / thresholds
    masks_kernel<<<cB, 256>>>(hs, msk, out_thr, wid, nb, ws, wise);
    // 2. xl = LN(x)
    ln_kernel<<<BT, 128>>>(x, nullptr, xl);
    // 3. local transformer (window-masked attention)
    run_transformer(xl, lWq, lWk, lWv, lWo, lW1, lW2,
                    lx, ls, /*mode=*/0, q, k, v, S, ao, pj, y, h, part, wid, nb);
    // 4. local_x *= wise
    scale_kernel<<<BT, 128>>>(lx, wise);
    // 5. pre[b,w,:] = sum_{t in window w} local_x[b,t,:] * local_score[b,t]
    pre_kernel<<<dim3(cT, cB), 128>>>(lx, ls, nb, ws, pre);
    // 6. preln = LN(pre)
    ln_kernel<<<BT, 128>>>(pre, nullptr, xl);
    // 7. global transformer (valid-window key mask)
    run_transformer(xl, gWq, gWk, gWv, gWo, gW1, gW2,
                    gy, h2, /*mode=*/1, q, k, v, S, ao, pj, y, h, part, wid, nb);
    // 8. data = local_x + gather(global_y)
    final_data<<<BT, 128>>>(lx, gy, wid, out);
    // 9. attn = softmax(local_score * gather(hh2))
    final_attn<<<cB, 256>>>(ls, h2, wid, out_attn);
}

// round 3
// speedup vs baseline: 2.3319x; 1.9457x over previous
#include <cuda_runtime.h>
#include <math.h>

// ---------------------------------------------------------------------------
// DWFormerBlock round 3: all GEMMs moved to TF32 tensor cores via
// mma.sync.aligned.m16n8k8 (fp32 accumulate, inputs rounded with cvt.rna.tf32).
// 128x128 / 128x64 CTA tiles, BK=16, double-buffered smem, conflict-free
// fragment loads. Non-GEMM kernels unchanged from R2.
// ---------------------------------------------------------------------------

constexpr int cB  = 16;
constexpr int cT  = 768;
constexpr int cF  = 512;
constexpr int cFF = 2048;
constexpr int cH  = 8;
constexpr int cDH = 64;
constexpr int BT  = cB * cT;       // 12288
constexpr int TT  = cT * cT;       // 589824
constexpr float NEGVAL = -1e30f;

// ------------------------------- scratch -----------------------------------
__device__ float g_xl [BT * cF];
__device__ float g_q  [BT * cF];
__device__ float g_k  [BT * cF];
__device__ float g_v  [BT * cF];
__device__ float g_S  [cB * cH * TT];     // 302 MB attention scores/probs
__device__ float g_ao [BT * cF];
__device__ float g_pj [BT * cF];
__device__ float g_y  [BT * cF];
__device__ float g_h  [BT * cFF];
__device__ float g_lx [BT * cF];
__device__ float g_gy [BT * cF];
__device__ float g_pre[BT * cF];
__device__ float g_ls [BT];
__device__ float g_h2 [BT];
__device__ float g_wise[BT];
__device__ float g_part[16 * BT];
__device__ int   g_wid[BT];
__device__ int   g_nb [cB];
__device__ int   g_ws [cB * (cT + 1)];

// --------------------------- small helpers ---------------------------------
__device__ __forceinline__ unsigned tf32r(float f) {
    unsigned u;
    asm("cvt.rna.tf32.f32 %0, %1;" : "=r"(u) : "f"(f));
    return u;
}

__device__ __forceinline__ void mma_tf32(float& d0, float& d1, float& d2, float& d3,
                                         unsigned a0, unsigned a1, unsigned a2, unsigned a3,
                                         unsigned b0, unsigned b1) {
    asm volatile(
        "mma.sync.aligned.m16n8k8.row.col.f32.tf32.tf32.f32 "
        "{%0,%1,%2,%3}, {%4,%5,%6,%7}, {%8,%9}, {%0,%1,%2,%3};"
        : "+f"(d0), "+f"(d1), "+f"(d2), "+f"(d3)
        : "r"(a0), "r"(a1), "r"(a2), "r"(a3), "r"(b0), "r"(b1));
}

__device__ __forceinline__ float redMax256(float v) {
    __shared__ float sm[8];
#pragma unroll
    for (int o = 16; o > 0; o >>= 1) v = fmaxf(v, __shfl_xor_sync(0xffffffffu, v, o));
    if ((threadIdx.x & 31) == 0) sm[threadIdx.x >> 5] = v;
    __syncthreads();
    if (threadIdx.x == 0) {
        float m = sm[0];
#pragma unroll
        for (int i = 1; i < 8; i++) m = fmaxf(m, sm[i]);
        sm[0] = m;
    }
    __syncthreads();
    float r = sm[0];
    __syncthreads();
    return r;
}

__device__ __forceinline__ float redSum256(float v) {
    __shared__ float sm[8];
#pragma unroll
    for (int o = 16; o > 0; o >>= 1) v += __shfl_xor_sync(0xffffffffu, v, o);
    if ((threadIdx.x & 31) == 0) sm[threadIdx.x >> 5] = v;
    __syncthreads();
    if (threadIdx.x == 0) {
        float s = 0.f;
#pragma unroll
        for (int i = 0; i < 8; i++) s += sm[i];
        sm[0] = s;
    }
    __syncthreads();
    float r = sm[0];
    __syncthreads();
    return r;
}

// ------------------------------- masks kernel ------------------------------
__global__ void masks_kernel(const float* __restrict__ hs, const float* __restrict__ msk,
                             float* __restrict__ thr_out, int* __restrict__ wid,
                             int* __restrict__ nbarr, int* __restrict__ ws,
                             float* __restrict__ wise) {
    int b = blockIdx.x, tid = threadIdx.x;
    __shared__ float ss[1024];
    __shared__ int a1[cT];
    __shared__ int x3[cT];
    __shared__ float red[256];
    __shared__ float sthr;

    for (int i = tid; i < 1024; i += 256)
        ss[i] = (i < cT) ? hs[b * cT + i] : 3.402823466e38f;
    __syncthreads();

    for (int k2 = 2; k2 <= 1024; k2 <<= 1) {
        for (int j = k2 >> 1; j > 0; j >>= 1) {
            for (int i = tid; i < 1024; i += 256) {
                int l = i ^ j;
                if (l > i) {
                    float a = ss[i], c = ss[l];
                    bool up = ((i & k2) == 0);
                    if ((a > c) == up) { ss[i] = c; ss[l] = a; }
                }
            }
            __syncthreads();
        }
    }

    float m1 = 0.f;
    for (int i = tid; i < cT; i += 256) m1 += 1.0f - msk[b * cT + i];
    red[tid] = m1; __syncthreads();
    for (int s = 128; s > 0; s >>= 1) {
        if (tid < s) red[tid] += red[tid + s];
        __syncthreads();
    }
    if (tid == 0) {
        float mm = red[0];
        int med = (int)(mm * 0.5f + (float)cT - mm);
        if (med > cT - 1) med = cT - 1;
        if (med < 0) med = 0;
        sthr = ss[med];
        thr_out[b] = sthr;
    }
    __syncthreads();
    float thr = sthr;

    for (int i = tid; i < cT; i += 256) {
        int keep = (hs[b * cT + i] >= thr) ? 1 : 0;
        a1[i] = keep;
        wise[b * cT + i] = keep ? 1.0f : 0.85f;
    }
    __syncthreads();
    for (int i = tid; i < cT; i += 256) {
        int x2 = (i < cT - 1) ? a1[i + 1] : (1 - a1[cT - 1]);
        x3[i] = (x2 != a1[i]) ? 1 : 0;
    }
    __syncthreads();
    if (tid == 0) {
        int c = 0;
        ws[b * (cT + 1)] = 0;
        int prev = 0;
        for (int t = 0; t < cT; t++) {
            int xt = x3[t];
            int xm = (xt == 1 && prev == 1) ? 0 : xt;
            if (t == cT - 1) xm = 1;
            prev = xt;
            wid[b * cT + t] = c;
            if (xm) { c++; ws[b * (cT + 1) + c] = t + 1; }
        }
        nbarr[b] = c;
    }
}

// ------------------------------ layernorm ----------------------------------
__global__ void ln_kernel(const float* __restrict__ X, const float* __restrict__ R,
                          float* __restrict__ Y) {
    long row = blockIdx.x;
    float4 v = ((const float4*)(X + row * cF))[threadIdx.x];
    if (R) {
        float4 r = ((const float4*)(R + row * cF))[threadIdx.x];
        v.x += r.x; v.y += r.y; v.z += r.z; v.w += r.w;
    }
    float s = v.x + v.y + v.z + v.w;
    float q = v.x * v.x + v.y * v.y + v.z * v.z + v.w * v.w;
    __shared__ float rs[4], rq[4];
#pragma unroll
    for (int o = 16; o > 0; o >>= 1) {
        s += __shfl_down_sync(0xffffffffu, s, o);
        q += __shfl_down_sync(0xffffffffu, q, o);
    }
    int w = threadIdx.x >> 5;
    if ((threadIdx.x & 31) == 0) { rs[w] = s; rq[w] = q; }
    __syncthreads();
    s = rs[0] + rs[1] + rs[2] + rs[3];
    q = rq[0] + rq[1] + rq[2] + rq[3];
    float mean = s * (1.0f / cF);
    float var  = q * (1.0f / cF) - mean * mean;
    float inv  = rsqrtf(var + 1e-5f);
    float4 o4 = make_float4((v.x - mean) * inv, (v.y - mean) * inv,
                            (v.z - mean) * inv, (v.w - mean) * inv);
    ((float4*)(Y + row * cF))[threadIdx.x] = o4;
}

// --------------------------- TF32 tensor GEMM ------------------------------
// C = alpha * A * op(B).  A row-major [M][K].  TRANSB ? B[N][K] : B[K][N].
// CTA tile BM x BN, BK = 16, NT threads (NT/32 warps laid out WM x WN).
// Per warp: (BM/WM) x (BN/WN) via m16n8k8 tf32 mma. Double-buffered smem.
template <int BM, int BN, int NT, int WM, int WN, bool TRANSB, bool RELU>
__global__ void __launch_bounds__(NT)
gemm_mma(const float* __restrict__ A, const float* __restrict__ Bm, float* __restrict__ C,
         int K, int lda, int ldb, int ldc,
         long sAb, long sAh, long sBb, long sBh, long sCb, long sCh,
         int Hdiv, float alpha) {
    constexpr int BK  = 16;
    constexpr int BKP = BK + 4;              // stride 20: conflict-free frags
    constexpr int BNP = BN + 8;              // stride%32==8: conflict-free frags
    constexpr int MT  = BM / WM / 16;        // m16 tiles per warp
    constexpr int NTT = BN / WN / 8;         // n8 tiles per warp
    constexpr int AI  = BM * BK / 4 / NT;    // float4 A loads per thread
    constexpr int BI  = BN * BK / 4 / NT;    // float4 B loads per thread
    static_assert(AI * NT * 4 == BM * BK, "A tile");
    static_assert(BI * NT * 4 == BN * BK, "B tile");

    int z  = blockIdx.z;
    int bb = z / Hdiv, hh = z - bb * Hdiv;
    A  += (long)bb * sAb + (long)hh * sAh;
    Bm += (long)bb * sBb + (long)hh * sBh;
    C  += (long)bb * sCb + (long)hh * sCh;

    __shared__ unsigned As[2][BM][BKP];
    __shared__ unsigned Bs[2][TRANSB ? BN : BK][TRANSB ? BKP : BNP];

    int tid  = threadIdx.x;
    int wid  = tid >> 5, lane = tid & 31;
    int g    = lane >> 2, c = lane & 3;
    int wm0  = (wid % WM) * (BM / WM);
    int wn0  = (wid / WM) * (BN / WN);
    int m0   = blockIdx.y * BM, n0 = blockIdx.x * BN;

    float acc[MT][NTT][4] = {};
    float4 pa[AI], pb[BI];

    auto loadA = [&](int k0) {
#pragma unroll
        for (int i = 0; i < AI; i++) {
            int e = tid + i * NT;
            int m = e / (BK / 4), kq = (e % (BK / 4)) * 4;
            pa[i] = *(const float4*)(A + (long)(m0 + m) * lda + k0 + kq);
        }
    };
    auto loadB = [&](int k0) {
#pragma unroll
        for (int i = 0; i < BI; i++) {
            int e = tid + i * NT;
            if (TRANSB) {
                int n = e / (BK / 4), kq = (e % (BK / 4)) * 4;
                pb[i] = *(const float4*)(Bm + (long)(n0 + n) * ldb + k0 + kq);
            } else {
                int kk = e / (BN / 4), nq = (e % (BN / 4)) * 4;
                pb[i] = *(const float4*)(Bm + (long)(k0 + kk) * ldb + n0 + nq);
            }
        }
    };
    auto stage = [&](int buf) {
#pragma unroll
        for (int i = 0; i < AI; i++) {
            int e = tid + i * NT;
            int m = e / (BK / 4), kq = (e % (BK / 4)) * 4;
            As[buf][m][kq + 0] = tf32r(pa[i].x);
            As[buf][m][kq + 1] = tf32r(pa[i].y);
            As[buf][m][kq + 2] = tf32r(pa[i].z);
            As[buf][m][kq + 3] = tf32r(pa[i].w);
        }
#pragma unroll
        for (int i = 0; i < BI; i++) {
            int e = tid + i * NT;
            if (TRANSB) {
                int n = e / (BK / 4), kq = (e % (BK / 4)) * 4;
                Bs[buf][n][kq + 0] = tf32r(pb[i].x);
                Bs[buf][n][kq + 1] = tf32r(pb[i].y);
                Bs[buf][n][kq + 2] = tf32r(pb[i].z);
                Bs[buf][n][kq + 3] = tf32r(pb[i].w);
            } else {
                int kk = e / (BN / 4), nq = (e % (BN / 4)) * 4;
                Bs[buf][kk][nq + 0] = tf32r(pb[i].x);
                Bs[buf][kk][nq + 1] = tf32r(pb[i].y);
                Bs[buf][kk][nq + 2] = tf32r(pb[i].z);
                Bs[buf][kk][nq + 3] = tf32r(pb[i].w);
            }
        }
    };

    loadA(0); loadB(0); stage(0);
    __syncthreads();

    int buf = 0;
    for (int k0 = 0; k0 < K; k0 += BK) {
        bool more = (k0 + BK) < K;
        if (more) { loadA(k0 + BK); loadB(k0 + BK); }

#pragma unroll
        for (int kk = 0; kk < BK; kk += 8) {
            unsigned af[MT][4];
#pragma unroll
            for (int i = 0; i < MT; i++) {
                int r0 = wm0 + i * 16 + g;
                af[i][0] = As[buf][r0][kk + c];
                af[i][1] = As[buf][r0 + 8][kk + c];
                af[i][2] = As[buf][r0][kk + c + 4];
                af[i][3] = As[buf][r0 + 8][kk + c + 4];
            }
            unsigned bf[NTT][2];
#pragma unroll
            for (int j = 0; j < NTT; j++) {
                int n = wn0 + j * 8 + g;
                if (TRANSB) {
                    bf[j][0] = Bs[buf][n][kk + c];
                    bf[j][1] = Bs[buf][n][kk + c + 4];
                } else {
                    bf[j][0] = Bs[buf][kk + c][n];
                    bf[j][1] = Bs[buf][kk + c + 4][n];
                }
            }
#pragma unroll
            for (int i = 0; i < MT; i++)
#pragma unroll
                for (int j = 0; j < NTT; j++)
                    mma_tf32(acc[i][j][0], acc[i][j][1], acc[i][j][2], acc[i][j][3],
                             af[i][0], af[i][1], af[i][2], af[i][3],
                             bf[j][0], bf[j][1]);
        }

        if (more) {
            int nb2 = buf ^ 1;
            stage(nb2);
            __syncthreads();
            buf = nb2;
        }
    }

    // ---- epilogue: c0=(g, c*2) c1=(g, c*2+1) c2=(g+8, c*2) c3=(g+8, c*2+1)
#pragma unroll
    for (int i = 0; i < MT; i++) {
#pragma unroll
        for (int j = 0; j < NTT; j++) {
            int row0 = m0 + wm0 + i * 16 + g;
            int col  = n0 + wn0 + j * 8 + c * 2;
            float2 lo, hi;
            lo.x = acc[i][j][0] * alpha; lo.y = acc[i][j][1] * alpha;
            hi.x = acc[i][j][2] * alpha; hi.y = acc[i][j][3] * alpha;
            if (RELU) {
                lo.x = fmaxf(lo.x, 0.f); lo.y = fmaxf(lo.y, 0.f);
                hi.x = fmaxf(hi.x, 0.f); hi.y = fmaxf(hi.y, 0.f);
            }
            *(float2*)(C + (long)row0 * ldc + col)       = lo;
            *(float2*)(C + (long)(row0 + 8) * ldc + col) = hi;
        }
    }
}

// ------------------------------ softmax ------------------------------------
__global__ void softmax_k(float* __restrict__ S, const int* __restrict__ wid,
                          const int* __restrict__ nbarr, int mode) {
    long r = blockIdx.x;
    int b  = (int)(r / ((long)cH * cT));
    int qi = (int)(r % cT);
    float* row = S + r * (long)cT;
    int tid = threadIdx.x;
    float xv[3];
    if (mode == 0) {
        int wq = __ldg(&wid[b * cT + qi]);
#pragma unroll
        for (int i = 0; i < 3; i++) {
            int k = tid + i * 256;
            float v = row[k];
            xv[i] = (__ldg(&wid[b * cT + k]) == wq) ? v : NEGVAL;
        }
    } else {
        int lim = __ldg(&nbarr[b]);
#pragma unroll
        for (int i = 0; i < 3; i++) {
            int k = tid + i * 256;
            float v = row[k];
            xv[i] = (k < lim) ? v : NEGVAL;
        }
    }
    float mx = redMax256(fmaxf(fmaxf(xv[0], xv[1]), xv[2]));
    float e[3];
    float s = 0.f;
#pragma unroll
    for (int i = 0; i < 3; i++) { e[i] = expf(xv[i] - mx); s += e[i]; }
    s = redSum256(s);
    float inv = 1.0f / s;
#pragma unroll
    for (int i = 0; i < 3; i++) row[tid + i * 256] = e[i] * inv;
}

// ------------------ column mean of probs (score / hh2) ---------------------
__global__ void colsum_part(const float* __restrict__ S, float* __restrict__ part) {
    int b = blockIdx.y;
    int k = blockIdx.x * 128 + threadIdx.x;
    int z = blockIdx.z;
    const int RPS = cH * cT / 16;             // 384
    const float* base = S + (long)b * cH * TT + (long)z * RPS * cT + k;
    float s = 0.f;
#pragma unroll 8
    for (int r = 0; r < RPS; r++) s += base[(long)r * cT];
    part[(long)z * BT + b * cT + k] = s;
}

__global__ void colsum_fin(const float* __restrict__ part, float* __restrict__ outv,
                           float scale) {
    int i = blockIdx.x * 256 + threadIdx.x;
    if (i < BT) {
        float s = 0.f;
#pragma unroll
        for (int z = 0; z < 16; z++) s += part[(long)z * BT + i];
        outv[i] = s * scale;
    }
}

// ------------------- window aggregation: pre[b,w,:] ------------------------
__global__ void pre_kernel(const float* __restrict__ lx, const float* __restrict__ ls,
                           const int* __restrict__ nbarr, const int* __restrict__ ws,
                           float* __restrict__ pre) {
    int b = blockIdx.y, w = blockIdx.x, tid = threadIdx.x;
    float4 acc = make_float4(0.f, 0.f, 0.f, 0.f);
    if (w < nbarr[b]) {
        int s = ws[b * (cT + 1) + w];
        int e = ws[b * (cT + 1) + w + 1];
        for (int t = s; t < e; t++) {
            float sc = __ldg(&ls[b * cT + t]);
            float4 v = ((const float4*)(lx + ((long)b * cT + t) * cF))[tid];
            acc.x = fmaf(v.x, sc, acc.x); acc.y = fmaf(v.y, sc, acc.y);
            acc.z = fmaf(v.z, sc, acc.z); acc.w = fmaf(v.w, sc, acc.w);
        }
    }
    ((float4*)(pre + ((long)b * cT + w) * cF))[tid] = acc;
}

// --------------------------- misc elementwise ------------------------------
__global__ void scale_kernel(float* __restrict__ yx, const float* __restrict__ wise) {
    long row = blockIdx.x;
    float sc = wise[row];
    float4 v = ((const float4*)(yx + row * cF))[threadIdx.x];
    v.x *= sc; v.y *= sc; v.z *= sc; v.w *= sc;
    ((float4*)(yx + row * cF))[threadIdx.x] = v;
}

__global__ void final_data(const float* __restrict__ lx, const float* __restrict__ gy,
                           const int* __restrict__ wid, float* __restrict__ outd) {
    long i = blockIdx.x;
    int b = (int)(i / cT);
    int w = wid[i];
    float4 a = ((const float4*)(lx + i * cF))[threadIdx.x];
    float4 g = ((const float4*)(gy + ((long)b * cT + w) * cF))[threadIdx.x];
    a.x += g.x; a.y += g.y; a.z += g.z; a.w += g.w;
    ((float4*)(outd + i * cF))[threadIdx.x] = a;
}

__global__ void final_attn(const float* __restrict__ ls, const float* __restrict__ h2,
                           const int* __restrict__ wid, float* __restrict__ outa) {
    int b = blockIdx.x, tid = threadIdx.x;
    float xv[3];
#pragma unroll
    for (int i = 0; i < 3; i++) {
        int t = tid + i * 256;
        xv[i] = ls[b * cT + t] * h2[b * cT + wid[b * cT + t]];
    }
    float mx = redMax256(fmaxf(fmaxf(xv[0], xv[1]), xv[2]));
    float e[3];
    float s = 0.f;
#pragma unroll
    for (int i = 0; i < 3; i++) { e[i] = expf(xv[i] - mx); s += e[i]; }
    s = redSum256(s);
    float inv = 1.0f / s;
#pragma unroll
    for (int i = 0; i < 3; i++) outa[b * cT + tid + i * 256] = e[i] * inv;
}

// ------------------------------ host side ----------------------------------
static void run_transformer(const float* xin,
                            const float* Wq, const float* Wk, const float* Wv,
                            const float* Wo, const float* W1, const float* W2,
                            float* yout, float* score, int mode,
                            float* q, float* k, float* v, float* S, float* ao,
                            float* pj, float* y, float* h, float* part,
                            const int* wid, const int* nb) {
    // QKV projections (dense 12288 x 512 x 512)
    gemm_mma<128, 128, 256, 2, 4, false, false><<<dim3(cF / 128, BT / 128, 1), 256>>>(
        xin, Wq, q, cF, cF, cF, cF, 0, 0, 0, 0, 0, 0, 1, 1.f);
    gemm_mma<128, 128, 256, 2, 4, false, false><<<dim3(cF / 128, BT / 128, 1), 256>>>(
        xin, Wk, k, cF, cF, cF, cF, 0, 0, 0, 0, 0, 0, 1, 1.f);
    gemm_mma<128, 128, 256, 2, 4, false, false><<<dim3(cF / 128, BT / 128, 1), 256>>>(
        xin, Wv, v, cF, cF, cF, cF, 0, 0, 0, 0, 0, 0, 1, 1.f);
    // scores = Q K^T / sqrt(dh)   (batched over B*H, K = 64)
    gemm_mma<128, 128, 256, 2, 4, true, false><<<dim3(cT / 128, cT / 128, cB * cH), 256>>>(
        q, k, S, cDH, cF, cF, cT,
        (long)cT * cF, (long)cDH, (long)cT * cF, (long)cDH,
        (long)cH * TT, (long)TT, cH, 0.125f);
    softmax_k<<<cB * cH * cT, 256>>>(S, wid, nb, mode);
    colsum_part<<<dim3(cT / 128, cB, 16), 128>>>(S, part);
    colsum_fin<<<(BT + 255) / 256, 256>>>(part, score, 1.0f / (cH * cT));
    // out = A V  (batched over B*H, N = 64)
    gemm_mma<128, 64, 256, 4, 2, false, false><<<dim3(1, cT / 128, cB * cH), 256>>>(
        S, v, ao, cT, cT, cF, cF,
        (long)cH * TT, (long)TT, (long)cT * cF, (long)cDH,
        (long)cT * cF, (long)cDH, cH, 1.f);
    // Wo projection, residual LN
    gemm_mma<128, 128, 256, 2, 4, false, false><<<dim3(cF / 128, BT / 128, 1), 256>>>(
        ao, Wo, pj, cF, cF, cF, cF, 0, 0, 0, 0, 0, 0, 1, 1.f);
    ln_kernel<<<BT, 128>>>(xin, pj, y);
    // FFN
    gemm_mma<128, 128, 256, 2, 4, false, true><<<dim3(cFF / 128, BT / 128, 1), 256>>>(
        y, W1, h, cF, cF, cFF, cFF, 0, 0, 0, 0, 0, 0, 1, 1.f);
    gemm_mma<128, 128, 256, 2, 4, false, false><<<dim3(cF / 128, BT / 128, 1), 256>>>(
        h, W2, pj, cFF, cFF, cF, cF, 0, 0, 0, 0, 0, 0, 1, 1.f);
    ln_kernel<<<BT, 128>>>(y, pj, yout);
}

extern "C" void kernel_launch(void* const* d_in, const int* in_sizes, int n_in,
                              void* d_out, int out_size) {
    (void)in_sizes; (void)n_in; (void)out_size;
    const float* x   = (const float*)d_in[0];
    const float* hs  = (const float*)d_in[1];
    const float* msk = (const float*)d_in[2];
    const float* lWq = (const float*)d_in[3];
    const float* lWk = (const float*)d_in[4];
    const float* lWv = (const float*)d_in[5];
    const float* lWo = (const float*)d_in[6];
    const float* lW1 = (const float*)d_in[7];
    const float* lW2 = (const float*)d_in[8];
    const float* gWq = (const float*)d_in[9];
    const float* gWk = (const float*)d_in[10];
    const float* gWv = (const float*)d_in[11];
    const float* gWo = (const float*)d_in[12];
    const float* gW1 = (const float*)d_in[13];
    const float* gW2 = (const float*)d_in[14];

    float* out      = (float*)d_out;
    float* out_thr  = out + (long)BT * cF;   // thresholds (B,)
    float* out_attn = out_thr + cB;          // attn (B, T)

    float *xl, *q, *k, *v, *S, *ao, *pj, *y, *h, *lx, *gy, *pre, *ls, *h2, *wise, *part;
    int *wid, *nb, *ws;
    cudaGetSymbolAddress((void**)&xl,   g_xl);
    cudaGetSymbolAddress((void**)&q,    g_q);
    cudaGetSymbolAddress((void**)&k,    g_k);
    cudaGetSymbolAddress((void**)&v,    g_v);
    cudaGetSymbolAddress((void**)&S,    g_S);
    cudaGetSymbolAddress((void**)&ao,   g_ao);
    cudaGetSymbolAddress((void**)&pj,   g_pj);
    cudaGetSymbolAddress((void**)&y,    g_y);
    cudaGetSymbolAddress((void**)&h,    g_h);
    cudaGetSymbolAddress((void**)&lx,   g_lx);
    cudaGetSymbolAddress((void**)&gy,   g_gy);
    cudaGetSymbolAddress((void**)&pre,  g_pre);
    cudaGetSymbolAddress((void**)&ls,   g_ls);
    cudaGetSymbolAddress((void**)&h2,   g_h2);
    cudaGetSymbolAddress((void**)&wise, g_wise);
    cudaGetSymbolAddress((void**)&part, g_part);
    cudaGetSymbolAddress((void**)&wid,  g_wid);
    cudaGetSymbolAddress((void**)&nb,   g_nb);
    cudaGetSymbolAddress((void**)&ws,   g_ws);

    // 1. masks / windows / thresholds
    masks_kernel<<<cB, 256>>>(hs, msk, out_thr, wid, nb, ws, wise);
    // 2. xl = LN(x)
    ln_kernel<<<BT, 128>>>(x, nullptr, xl);
    // 3. local transformer (window-masked attention)
    run_transformer(xl, lWq, lWk, lWv, lWo, lW1, lW2,
                    lx, ls, /*mode=*/0, q, k, v, S, ao, pj, y, h, part, wid, nb);
    // 4. local_x *= wise
    scale_kernel<<<BT, 128>>>(lx, wise);
    // 5. pre[b,w,:] = sum_{t in window w} local_x[b,t,:] * local_score[b,t]
    pre_kernel<<<dim3(cT, cB), 128>>>(lx, ls, nb, ws, pre);
    // 6. preln = LN(pre)
    ln_kernel<<<BT, 128>>>(pre, nullptr, xl);
    // 7. global transformer (valid-window key mask)
    run_transformer(xl, gWq, gWk, gWv, gWo, gW1, gW2,
                    gy, h2, /*mode=*/1, q, k, v, S, ao, pj, y, h, part, wid, nb);
    // 8. data = local_x + gather(global_y)
    final_data<<<BT, 128>>>(lx, gy, wid, out);
    // 9. attn = softmax(local_score * gather(hh2))
    final_attn<<<cB, 256>>>(ls, h2, wid, out_attn);
}